// round 3
// baseline (speedup 1.0000x reference)
#include <cuda_runtime.h>

#define BS    2048
#define NINP  512
#define NHID  512
#define KBLK  16
#define TT    8
#define MM    32
#define NTOT  (BS*KBLK)        // 32768
#define GI_COLS (TT*3*MM)      // 768
#define TPB   448              // 14 warps; grid 147 ~= #SMs

// scratch for gi = x @ W_ih^T + b_ih, per-b (k-independent)
__device__ float g_gi[BS * GI_COLS];   // [2048][768], 6 MB

// ---------------------------------------------------------------------------
// Kernel 1: gi[b][t*96+g] = sum_k x[b][k]*W_ih[t][g][k] + b_ih[t][g]
// ---------------------------------------------------------------------------
__global__ void __launch_bounds__(256) gemm_gi_kernel(
    const float* __restrict__ A,
    const float* __restrict__ B,
    const float* __restrict__ bias)
{
    __shared__ float As[32][65];
    __shared__ float Bs[32][65];

    const int tid = threadIdx.x;
    const int tx  = tid & 15;
    const int ty  = tid >> 4;
    const int m0  = blockIdx.y * 64;
    const int n0  = blockIdx.x * 64;
    const int lr  = tid >> 3;
    const int lk  = (tid & 7) * 4;

    float acc[4][4];
#pragma unroll
    for (int i = 0; i < 4; i++)
#pragma unroll
        for (int j = 0; j < 4; j++) acc[i][j] = 0.f;

    for (int k0 = 0; k0 < NINP; k0 += 32) {
#pragma unroll
        for (int r = 0; r < 2; r++) {
            float4 va = *(const float4*)&A[(m0 + lr + r * 32) * NINP + k0 + lk];
            As[lk + 0][lr + r * 32] = va.x;
            As[lk + 1][lr + r * 32] = va.y;
            As[lk + 2][lr + r * 32] = va.z;
            As[lk + 3][lr + r * 32] = va.w;
            float4 vb = *(const float4*)&B[(n0 + lr + r * 32) * NINP + k0 + lk];
            Bs[lk + 0][lr + r * 32] = vb.x;
            Bs[lk + 1][lr + r * 32] = vb.y;
            Bs[lk + 2][lr + r * 32] = vb.z;
            Bs[lk + 3][lr + r * 32] = vb.w;
        }
        __syncthreads();
#pragma unroll
        for (int k = 0; k < 32; k++) {
            float a[4], b[4];
#pragma unroll
            for (int i = 0; i < 4; i++) a[i] = As[k][ty + i * 16];
#pragma unroll
            for (int j = 0; j < 4; j++) b[j] = Bs[k][tx + j * 16];
#pragma unroll
            for (int i = 0; i < 4; i++)
#pragma unroll
                for (int j = 0; j < 4; j++)
                    acc[i][j] = fmaf(a[i], b[j], acc[i][j]);
        }
        __syncthreads();
    }

#pragma unroll
    for (int j = 0; j < 4; j++) {
        float bj = bias[n0 + tx + j * 16];
#pragma unroll
        for (int i = 0; i < 4; i++)
            g_gi[(m0 + ty + i * 16) * GI_COLS + n0 + tx + j * 16] = acc[i][j] + bj;
    }
}

// ---------------------------------------------------------------------------
// Kernel 2: pair-of-threads-per-n fused GRU + attention + hard gumbel select.
// Lane half = tid&1 handles hidden units [half*16, half*16+16).
// ---------------------------------------------------------------------------
#define SMEM_FLOATS (TT*96*MM + TT*MM*16 + MM*16 + TT*96)   // 29952
#define SMEM_BYTES  (SMEM_FLOATS * 4)                        // 119808

__global__ void __launch_bounds__(TPB, 1) fused3_kernel(
    const float* __restrict__ h,
    const float* __restrict__ W_hh,
    const float* __restrict__ b_hh,
    const float* __restrict__ w_read,
    const float* __restrict__ w_write,
    const float* __restrict__ gum,
    float* __restrict__ out)
{
    extern __shared__ float sm[];
    float* Wg  = sm;               // W_hh natural layout [t][g][m]: 24576
    float* Wwr = Wg + TT*96*MM;    // w_write [t][l][f]:             4096
    float* Wrd = Wwr + TT*MM*16;   // w_read [m][f]:                  512
    float* bh  = Wrd + MM*16;      // b_hh [t][g]:                    768
    const int tid = threadIdx.x;

    {   // stage weights (contiguous float4 copies)
        float4* d = (float4*)Wg; const float4* s = (const float4*)W_hh;
        for (int i = tid; i < TT*96*MM/4; i += TPB) d[i] = s[i];
        d = (float4*)Wwr; s = (const float4*)w_write;
        for (int i = tid; i < TT*MM*16/4; i += TPB) d[i] = s[i];
        d = (float4*)Wrd; s = (const float4*)w_read;
        for (int i = tid; i < MM*16/4; i += TPB) d[i] = s[i];
        d = (float4*)bh; s = (const float4*)b_hh;
        for (int i = tid; i < TT*96/4; i += TPB) d[i] = s[i];
    }
    __syncthreads();

    const int gtid = blockIdx.x * TPB + tid;
    if (gtid >= 2 * NTOT) return;           // whole trailing warps exit
    const int n    = gtid >> 1;
    const int half = gtid & 1;
    const int l0   = half * 16;
    const int b    = n >> 4;

    float h2[32];
    {
        const float4* hp = (const float4*)(h + n * MM);
#pragma unroll
        for (int i = 0; i < 8; i++) {
            float4 v = hp[i];
            h2[4*i] = v.x; h2[4*i+1] = v.y; h2[4*i+2] = v.z; h2[4*i+3] = v.w;
        }
    }

    // h_read[f] = sum_m h2[m] * w_read[m][f]  (computed in both pair threads)
    float hr[16];
#pragma unroll
    for (int f = 0; f < 16; f++) hr[f] = 0.f;
#pragma unroll
    for (int m = 0; m < 32; m++) {
        const float4* w = (const float4*)(Wrd + m * 16);
        float hm = h2[m];
#pragma unroll
        for (int f4 = 0; f4 < 4; f4++) {
            float4 v = w[f4];
            hr[4*f4]   = fmaf(hm, v.x, hr[4*f4]);
            hr[4*f4+1] = fmaf(hm, v.y, hr[4*f4+1]);
            hr[4*f4+2] = fmaf(hm, v.z, hr[4*f4+2]);
            hr[4*f4+3] = fmaf(hm, v.w, hr[4*f4+3]);
        }
    }

    // gumbel noise prefetch
    float g8[8];
    {
        const float4* gp = (const float4*)(gum + n * TT);
        float4 a = gp[0], c = gp[1];
        g8[0]=a.x; g8[1]=a.y; g8[2]=a.z; g8[3]=a.w;
        g8[4]=c.x; g8[5]=c.y; g8[6]=c.z; g8[7]=c.w;
    }

    float rmax = -1e30f, rsum = 0.f;
    int amax = 0;
    float hsel[16], hcur[16];
#pragma unroll
    for (int i = 0; i < 16; i++) hsel[i] = 0.f;

#pragma unroll 1
    for (int t = 0; t < TT; t++) {
        const float* gib = g_gi + b * GI_COLS + t * 96;
        const float* wt  = Wg  + t * 96 * MM;
        const float* wwt = Wwr + t * MM * 16;
        const float* bht = bh  + t * 96;
        float lgp = 0.f;

#pragma unroll 2
        for (int l4 = 0; l4 < 4; l4++) {
            float Ga[4], Gb[4], Gc[4];
            *(float4*)Ga = *(const float4*)(gib + l0 + 4*l4);
            *(float4*)Gb = *(const float4*)(gib + 32 + l0 + 4*l4);
            *(float4*)Gc = *(const float4*)(gib + 64 + l0 + 4*l4);
#pragma unroll
            for (int li = 0; li < 4; li++) {
                const int l = l0 + 4*l4 + li;
                float ar = bht[l], az = bht[32 + l], an = bht[64 + l];
                const float4* wr = (const float4*)(wt + l * 32);
                const float4* wz = (const float4*)(wt + (32 + l) * 32);
                const float4* wn = (const float4*)(wt + (64 + l) * 32);
#pragma unroll
                for (int m4 = 0; m4 < 8; m4++) {
                    float4 a = wr[m4], bb = wz[m4], c = wn[m4];
                    ar = fmaf(a.x,  h2[4*m4],   ar);
                    ar = fmaf(a.y,  h2[4*m4+1], ar);
                    ar = fmaf(a.z,  h2[4*m4+2], ar);
                    ar = fmaf(a.w,  h2[4*m4+3], ar);
                    az = fmaf(bb.x, h2[4*m4],   az);
                    az = fmaf(bb.y, h2[4*m4+1], az);
                    az = fmaf(bb.z, h2[4*m4+2], az);
                    az = fmaf(bb.w, h2[4*m4+3], az);
                    an = fmaf(c.x,  h2[4*m4],   an);
                    an = fmaf(c.y,  h2[4*m4+1], an);
                    an = fmaf(c.z,  h2[4*m4+2], an);
                    an = fmaf(c.w,  h2[4*m4+3], an);
                }
                // av = w_write[t][l] . h_read   (16-wide dot)
                const float4* ww = (const float4*)(wwt + l * 16);
                float4 w0 = ww[0], w1 = ww[1], w2 = ww[2], w3 = ww[3];
                float av;
                av = w0.x * hr[0];
                av = fmaf(w0.y, hr[1],  av);
                av = fmaf(w0.z, hr[2],  av);
                av = fmaf(w0.w, hr[3],  av);
                av = fmaf(w1.x, hr[4],  av);
                av = fmaf(w1.y, hr[5],  av);
                av = fmaf(w1.z, hr[6],  av);
                av = fmaf(w1.w, hr[7],  av);
                av = fmaf(w2.x, hr[8],  av);
                av = fmaf(w2.y, hr[9],  av);
                av = fmaf(w2.z, hr[10], av);
                av = fmaf(w2.w, hr[11], av);
                av = fmaf(w3.x, hr[12], av);
                av = fmaf(w3.y, hr[13], av);
                av = fmaf(w3.z, hr[14], av);
                av = fmaf(w3.w, hr[15], av);

                float r  = __fdividef(1.f, 1.f + __expf(-(Ga[li] + ar)));
                float z  = __fdividef(1.f, 1.f + __expf(-(Gb[li] + az)));
                float xn = Gc[li] + r * an;
                float e2 = __expf(-2.f * xn);
                float nn = __fdividef(1.f - e2, 1.f + e2);   // tanh
                float hn = (1.f - z) * nn + z * h2[l];
                hcur[4*l4 + li] = hn;
                lgp = fmaf(hn, av, lgp);
            }
        }
        // combine pair halves: one shuffle (commutative add -> identical both)
        float lg = lgp + __shfl_xor_sync(0xffffffffu, lgp, 1);
        float s  = (lg + g8[t]) * 2.0f;     // /TAU, TAU=0.5
        if (s > rmax) {
            rsum = rsum * __expf(rmax - s) + 1.f;
            rmax = s; amax = t;
#pragma unroll
            for (int i = 0; i < 16; i++) hsel[i] = hcur[i];
        } else {
            rsum += __expf(s - rmax);
        }
    }

    float p = __fdividef(1.f, rsum);        // softmax value at argmax
    float attv = (1.f + p) - p;             // straight-through residual, exact

    float4* ho = (float4*)(out + n * MM + l0);
#pragma unroll
    for (int l4 = 0; l4 < 4; l4++) {
        float4 v;
        v.x = attv * hsel[4*l4];
        v.y = attv * hsel[4*l4+1];
        v.z = attv * hsel[4*l4+2];
        v.w = attv * hsel[4*l4+3];
        ho[l4] = v;
    }
    if (half == 0) {
        float* ao = out + BS * NHID + n * TT;
#pragma unroll
        for (int t = 0; t < TT; t++) ao[t] = (t == amax) ? attv : 0.f;
    }
}

// ---------------------------------------------------------------------------
extern "C" void kernel_launch(void* const* d_in, const int* in_sizes, int n_in,
                              void* d_out, int out_size)
{
    const float* x       = (const float*)d_in[0];
    const float* h       = (const float*)d_in[1];
    const float* W_ih    = (const float*)d_in[2];
    const float* W_hh    = (const float*)d_in[3];
    const float* b_ih    = (const float*)d_in[4];
    const float* b_hh    = (const float*)d_in[5];
    const float* w_read  = (const float*)d_in[6];
    const float* w_write = (const float*)d_in[7];
    const float* gum     = (const float*)d_in[8];
    float* out = (float*)d_out;

    dim3 g1(GI_COLS / 64, BS / 64);           // (12, 32)
    gemm_gi_kernel<<<g1, 256>>>(x, W_ih, b_ih);

    cudaFuncSetAttribute(fused3_kernel,
                         cudaFuncAttributeMaxDynamicSharedMemorySize, SMEM_BYTES);
    fused3_kernel<<<(2 * NTOT + TPB - 1) / TPB, TPB, SMEM_BYTES>>>(
        h, W_hh, b_hh, w_read, w_write, gum, out);
}